// round 13
// baseline (speedup 1.0000x reference)
#include <cuda_runtime.h>
#include <cuda_fp16.h>
#include <cstdint>
#include <math.h>

// LayerGate as one GEMM D[65536,512] = X[65536,512] @ W_aug[512,512] (per j-block),
// fp16 single-pass mma.sync.m16n8k16 (fp32 acc), fused gate epilogue.
// CTA tile 256x128, warp tile 64x64 (LDSM/MMA ratio 0.25), 4-stage cp.async pipeline
// (K-slice 64, 48KB/stage), 1 CTA/SM. A planes deduplicated (CNN + gaz/gazb/gm/exp).
// Weight columns reordered n' = h*4 + g so a 128-col CTA tile holds all 4 gate groups.

namespace {
constexpr int STAGE_BYTES = 49152;    // per stage: A 32KB (256 rows) + B 16KB (128 rows)
constexpr int NSTAGE      = 4;
constexpr int SMEM_TOTAL  = 196608;   // 4 stages; front 128KB reused as 256x128 fp32 gate tile
}

// Dedup'd fp16 A planes (row stride 256B = 128 fp16)
__device__ __align__(16) unsigned char g_a0[65536ull * 256];  // CNN  [r][128]   16.8MB
__device__ __align__(16) unsigned char g_agf[16384ull * 256]; // gaz  [b*512+s]  4.2MB
__device__ __align__(16) unsigned char g_agb[16384ull * 256]; // gazb            4.2MB
__device__ __align__(16) unsigned char g_agm[16384ull * 256]; // gm              4.2MB
__device__ __align__(16) unsigned char g_aex[16384ull * 256]; // exp             4.2MB
// [j][n'][k] fp16, n'=512 reordered cols = 2MB
__device__ __align__(16) unsigned char g_wh[4ull * 512 * 1024];

// ---------- PTX helpers (compute_80-level; safe under .target sm_103) ----------
__device__ __forceinline__ uint32_t smem_u32(const void* p) {
    uint32_t a;
    asm("{ .reg .u64 t; cvta.to.shared.u64 t, %1; cvt.u32.u64 %0, t; }" : "=r"(a) : "l"(p));
    return a;
}
__device__ __forceinline__ void cp16(uint32_t dst, const void* src) {
    asm volatile("cp.async.cg.shared.global [%0], [%1], 16;" :: "r"(dst), "l"(src));
}
__device__ __forceinline__ void cp_commit() {
    asm volatile("cp.async.commit_group;" ::: "memory");
}
__device__ __forceinline__ void cp_wait2() {
    asm volatile("cp.async.wait_group 2;" ::: "memory");
}
__device__ __forceinline__ void ldsm4(uint32_t* r, uint32_t addr) {
    asm volatile("ldmatrix.sync.aligned.m8n8.x4.shared.b16 {%0,%1,%2,%3}, [%4];"
                 : "=r"(r[0]), "=r"(r[1]), "=r"(r[2]), "=r"(r[3]) : "r"(addr));
}
__device__ __forceinline__ void mma_fp16(float* d, const uint32_t* a, const uint32_t* b) {
    asm volatile("mma.sync.aligned.m16n8k16.row.col.f32.f16.f16.f32 "
                 "{%0,%1,%2,%3}, {%4,%5,%6,%7}, {%8,%9}, {%0,%1,%2,%3};"
                 : "+f"(d[0]), "+f"(d[1]), "+f"(d[2]), "+f"(d[3])
                 : "r"(a[0]), "r"(a[1]), "r"(a[2]), "r"(a[3]), "r"(b[0]), "r"(b[1]));
}

// ---------- Prep: dedup'd fp16 planes + weights, one launch ----------
// blocks [0,8192): CNN; [8192,10240): gaz; [10240,12288): gazb;
// [12288,14336): gm; [14336,16384): exp; [16384,17408): weights
__global__ void __launch_bounds__(256) wprep(const float* __restrict__ cnn,
                                             const float* __restrict__ gaz,
                                             const float* __restrict__ gazb,
                                             const float* __restrict__ gm,
                                             const float* __restrict__ expi,
                                             const float* __restrict__ Wcat,
                                             const float* __restrict__ Wexp)
{
    const int bx = blockIdx.x;
    if (bx < 16384) {
        const float* src;
        unsigned char* dst;
        int idx;
        if (bx < 8192) {            // CNN: 65536 rows x 32 k4
            idx = bx * 256 + threadIdx.x;
            int r = idx >> 5;
            int j = r >> 14, b = (r >> 9) & 31, s = r & 511;
            src = cnn + ((size_t)(b * 2048 + j * 512 + s) << 7);
            dst = g_a0 + (size_t)r * 256;
        } else {                    // 16384 rows x 32 k4 each
            int grp = (bx - 8192) >> 11;            // 0..3
            idx = ((bx - 8192) & 2047) * 256 + threadIdx.x;
            int rr = idx >> 5;
            const float* base = (grp == 0) ? gaz : (grp == 1) ? gazb : (grp == 2) ? gm : expi;
            unsigned char* pl  = (grp == 0) ? g_agf : (grp == 1) ? g_agb : (grp == 2) ? g_agm : g_aex;
            src = base + ((size_t)rr << 7);
            dst = pl + (size_t)rr * 256;
        }
        int k4 = idx & 31;
        float4 v = *reinterpret_cast<const float4*>(src + k4 * 4);
        __half2 h0 = __floats2half2_rn(v.x, v.y);
        __half2 h1 = __floats2half2_rn(v.z, v.w);
        *reinterpret_cast<uint2*>(dst + k4 * 8) =
            make_uint2(*reinterpret_cast<uint32_t*>(&h0), *reinterpret_cast<uint32_t*>(&h1));
    } else {
        // weights -> g_wh, columns reordered n' = h*4+g
        int idx = (bx - 16384) * 256 + threadIdx.x;
        int h = idx & 127;
        int k = (idx >> 7) & 511;
        int j = idx >> 16;
#pragma unroll
        for (int g = 0; g < 4; g++) {
            float v;
            if (k < 384)     v = Wcat[(size_t)k * 2048 + j * 512 + g * 128 + h];
            else if (g >= 1) v = Wexp[(size_t)(k - 384) * 1536 + j * 384 + (g - 1) * 128 + h];
            else             v = 0.f;
            int npr = h * 4 + g;
            *reinterpret_cast<__half*>(g_wh + ((size_t)(j * 512) + npr) * 1024 + k * 2) =
                __float2half_rn(v);
        }
    }
}

// ---------- Main: 4-stage pipelined fp16 HMMA GEMM (64x64 warp tiles) + fused epilogue ----------
__global__ void __launch_bounds__(256, 1)
layergate_mma(const float* __restrict__ cnn,
              const float* __restrict__ expi,
              const float* __restrict__ bcat,
              const float* __restrict__ bexp,
              float* __restrict__ out)
{
    extern __shared__ __align__(1024) unsigned char smem[];
    const uint32_t sbase = smem_u32(smem);
    const int tid  = threadIdx.x;
    const int lane = tid & 31;
    const int wid  = tid >> 5;
    const int wm   = wid & 3;     // 4 warps in M (64 rows each)
    const int wn   = wid >> 2;    // 2 warps in N (64 cols each)
    const int nt   = blockIdx.x;  // 0..3   (h-block of 32)
    const int mx   = blockIdx.y;  // 0..63  (256-row tile within j)
    const int j    = blockIdx.z;  // 0..3
    const int rbase = j * 16384 + mx * 256;
    const int b    = mx >> 1;            // batch of this tile
    const int s0   = (mx & 1) * 256;     // sequence offset of row 0

    // Per-chunk A plane row-0 pointers (row stride 256B)
    const unsigned char* aplane[4];
    aplane[0] = g_a0 + (size_t)rbase * 256;
    aplane[1] = ((j & 1) ? g_agb : g_agf) + (size_t)(b * 512 + s0) * 256;
    aplane[2] = g_agm + (size_t)(b * 512 + s0) * 256;
    aplane[3] = g_aex + (size_t)(b * 512 + s0) * 256;

    float acc[4][8][4];
#pragma unroll
    for (int mf = 0; mf < 4; mf++)
#pragma unroll
        for (int nf = 0; nf < 8; nf++)
#pragma unroll
            for (int c = 0; c < 4; c++) acc[mf][nf][c] = 0.f;

    // ---- cp.async stage loader: A 32KB (2048 chunks) + B 16KB (1024 chunks), 12/thread
    auto issue_stage = [&](int s) {
        const uint32_t dstStage = sbase + (s & (NSTAGE - 1)) * STAGE_BYTES;
        const unsigned char* ap = aplane[s >> 1];
        const int koffB = (s & 1) * 128;          // byte offset within 256B row
#pragma unroll
        for (int i = 0; i < 8; i++) {
            int c = i * 256 + tid;                 // 2048 A chunks
            int r = c >> 3, ch = c & 7;
            const unsigned char* src = ap + (size_t)r * 256 + koffB + ch * 16;
            cp16(dstStage + r * 128 + ((ch ^ (r & 7)) * 16), src);
        }
#pragma unroll
        for (int i = 0; i < 4; i++) {
            int c = i * 256 + tid;                 // 1024 B chunks
            int r = c >> 3, ch = c & 7;
            const unsigned char* src =
                g_wh + ((size_t)(j * 512) + nt * 128 + r) * 1024 + s * 128 + ch * 16;
            cp16(dstStage + 32768 + r * 128 + ((ch ^ (r & 7)) * 16), src);
        }
        cp_commit();
    };

    // ldmatrix lane geometry
    const int arow = lane & 15;
    const int ac   = lane >> 4;
    const int brow = (lane & 7) | ((lane >> 4) << 3);
    const int bc   = (lane >> 3) & 1;

    auto compute_stage = [&](int s) {
        const uint32_t st = sbase + (s & (NSTAGE - 1)) * STAGE_BYTES;
        const uint32_t aBase = st + (wm * 64 + arow) * 128;
        const uint32_t bBase = st + 32768 + (wn * 64 + brow) * 128;
#pragma unroll
        for (int kk = 0; kk < 4; kk++) {
            const uint32_t aoff = ((kk * 2 + ac) ^ (arow & 7)) * 16;
            const uint32_t boff = ((kk * 2 + bc) ^ (brow & 7)) * 16;
            uint32_t A[4][4];
#pragma unroll
            for (int mf = 0; mf < 4; mf++) ldsm4(A[mf], aBase + mf * 2048 + aoff);
            uint32_t B[8][2];
#pragma unroll
            for (int ng = 0; ng < 4; ng++) {
                uint32_t t[4];
                ldsm4(t, bBase + ng * 2048 + boff);
                B[2 * ng][0] = t[0]; B[2 * ng][1] = t[1];
                B[2 * ng + 1][0] = t[2]; B[2 * ng + 1][1] = t[3];
            }
#pragma unroll
            for (int mf = 0; mf < 4; mf++)
#pragma unroll
                for (int nf = 0; nf < 8; nf++)
                    mma_fp16(acc[mf][nf], A[mf], B[nf]);
        }
    };

    issue_stage(0);
    issue_stage(1);
    issue_stage(2);
    for (int s = 0; s < 8; s++) {
        cp_wait2();                      // stage s landed (s+1, s+2 may still fly)
        __syncthreads();                 // all warps past compute(s-1); buf (s+3)&3 free
        if (s + 3 < 8) issue_stage(s + 3);
        else           cp_commit();      // empty group keeps wait arithmetic exact
        compute_stage(s);
    }

    // ---- Epilogue phase 1: dump acc to smem gate tile [256 rows][128 n'] fp32
    __syncthreads();
    float* gate = reinterpret_cast<float*>(smem);
    const int gid = lane >> 2, tig = lane & 3;
#pragma unroll
    for (int mf = 0; mf < 4; mf++)
#pragma unroll
        for (int nf = 0; nf < 8; nf++) {
            int row = wm * 64 + mf * 16 + gid;
            int col = wn * 64 + nf * 8 + tig * 2;
            *reinterpret_cast<float2*>(gate + row * 128 + col) =
                make_float2(acc[mf][nf][0], acc[mf][nf][1]);
            *reinterpret_cast<float2*>(gate + (row + 8) * 128 + col) =
                make_float2(acc[mf][nf][2], acc[mf][nf][3]);
        }
    __syncthreads();

    // ---- Epilogue phase 2: per (row, h) gather float4 {ns,g1,g2,g3}, finish, store
    const int hl = lane;
    const int hg = nt * 32 + hl;
    const float bc0 = bcat[j * 512 + hg];
    const float bc1 = bcat[j * 512 + 128 + hg];
    const float bc2 = bcat[j * 512 + 256 + hg];
    const float bc3 = bcat[j * 512 + 384 + hg];
    const float be1 = bexp[j * 384 + hg];
    const float be2 = bexp[j * 384 + 128 + hg];
    const float be3 = bexp[j * 384 + 256 + hg];
#pragma unroll
    for (int i = 0; i < 32; i++) {
        const int row = wid * 32 + i;
        const int srow = s0 + row;
        float4 gv = *reinterpret_cast<const float4*>(gate + row * 128 + hl * 4);
        float s1 = cnn[((size_t)(b * 2048 + j * 512 + srow) << 7) + hg];
        float s2 = expi[((size_t)(b * 512 + srow) << 7) + hg];
        float ns = tanhf(gv.x + bc0);
        float g1 = 1.f / (1.f + __expf(-(gv.y + bc1 + be1)));
        float g2 = 1.f / (1.f + __expf(-(gv.z + bc2 + be2)));
        float g3 = 1.f / (1.f + __expf(-(gv.w + bc3 + be3)));
        float e1 = __expf(g1), e2 = __expf(g2), e3 = __expf(g3);
        float inv = 1.f / (e1 + e2 + e3);
        out[((size_t)(rbase + row) << 7) + hg] = (e1 * ns + e2 * s1 + e3 * s2) * inv;
    }
}

extern "C" void kernel_launch(void* const* d_in, const int* in_sizes, int n_in,
                              void* d_out, int out_size)
{
    const float* cnn  = (const float*)d_in[0];
    const float* gaz  = (const float*)d_in[1];
    const float* gazb = (const float*)d_in[2];
    const float* gm   = (const float*)d_in[3];
    const float* expi = (const float*)d_in[4];
    const float* Wcat = (const float*)d_in[5];
    const float* bcat = (const float*)d_in[6];
    const float* Wexp = (const float*)d_in[7];
    const float* bexp = (const float*)d_in[8];
    float* out = (float*)d_out;

    wprep<<<17408, 256>>>(cnn, gaz, gazb, gm, expi, Wcat, Wexp);

    cudaFuncSetAttribute(layergate_mma,
                         cudaFuncAttributeMaxDynamicSharedMemorySize, SMEM_TOTAL);
    layergate_mma<<<dim3(4, 64, 4), 256, SMEM_TOTAL>>>(cnn, expi, bcat, bexp, out);
}

// round 14
// speedup vs baseline: 2.1116x; 2.1116x over previous
#include <cuda_runtime.h>
#include <cuda_fp16.h>
#include <cstdint>
#include <math.h>

// LayerGate as one GEMM D[65536,512] = X[65536,512] @ W_aug[512,512] (per j-block),
// fp16 single-pass mma.sync.m16n8k16 (fp32 acc), fused gate epilogue.
// 3-stage cp.async pipeline (K=64/stage), 2 CTAs/SM (<=128 regs), B-fragment
// double-buffer software pipeline. Dedup'd fp16 A planes (CNN + gaz/gazb/gm/exp).
// Weight columns reordered n' = h*4 + g so a 128-col CTA tile holds all 4 gate groups.

namespace {
constexpr int STAGE_BYTES = 32768;   // per stage: A 16KB + B 16KB (K=64 slice)
constexpr int NSTAGE      = 3;
constexpr int SMEM_TOTAL  = 98304;   // 3 stages (front 64KB reused as gate tile)
}

// Dedup'd fp16 A planes (row stride 256B = 128 fp16)
__device__ __align__(16) unsigned char g_a0[65536ull * 256];  // CNN  [r][128]
__device__ __align__(16) unsigned char g_agf[16384ull * 256]; // gaz  [b*512+s]
__device__ __align__(16) unsigned char g_agb[16384ull * 256]; // gazb
__device__ __align__(16) unsigned char g_agm[16384ull * 256]; // gm
__device__ __align__(16) unsigned char g_aex[16384ull * 256]; // exp
// [j][n'][k] fp16, n'=512 reordered cols = 2MB
__device__ __align__(16) unsigned char g_wh[4ull * 512 * 1024];

// ---------- PTX helpers (compute_80-level; safe under .target sm_103) ----------
__device__ __forceinline__ uint32_t smem_u32(const void* p) {
    uint32_t a;
    asm("{ .reg .u64 t; cvta.to.shared.u64 t, %1; cvt.u32.u64 %0, t; }" : "=r"(a) : "l"(p));
    return a;
}
__device__ __forceinline__ void cp16(uint32_t dst, const void* src) {
    asm volatile("cp.async.cg.shared.global [%0], [%1], 16;" :: "r"(dst), "l"(src));
}
__device__ __forceinline__ void cp_commit() {
    asm volatile("cp.async.commit_group;" ::: "memory");
}
__device__ __forceinline__ void cp_wait1() {
    asm volatile("cp.async.wait_group 1;" ::: "memory");
}
__device__ __forceinline__ void ldsm4(uint32_t* r, uint32_t addr) {
    asm volatile("ldmatrix.sync.aligned.m8n8.x4.shared.b16 {%0,%1,%2,%3}, [%4];"
                 : "=r"(r[0]), "=r"(r[1]), "=r"(r[2]), "=r"(r[3]) : "r"(addr));
}
__device__ __forceinline__ void mma_fp16(float* d, const uint32_t* a, const uint32_t* b) {
    asm volatile("mma.sync.aligned.m16n8k16.row.col.f32.f16.f16.f32 "
                 "{%0,%1,%2,%3}, {%4,%5,%6,%7}, {%8,%9}, {%0,%1,%2,%3};"
                 : "+f"(d[0]), "+f"(d[1]), "+f"(d[2]), "+f"(d[3])
                 : "r"(a[0]), "r"(a[1]), "r"(a[2]), "r"(a[3]), "r"(b[0]), "r"(b[1]));
}

// ---------- Prep: dedup'd fp16 planes + weights, one launch ----------
// blocks [0,8192): CNN; [8192,16384): gaz/gazb/gm/exp; [16384,17408): weights
__global__ void __launch_bounds__(256) wprep(const float* __restrict__ cnn,
                                             const float* __restrict__ gaz,
                                             const float* __restrict__ gazb,
                                             const float* __restrict__ gm,
                                             const float* __restrict__ expi,
                                             const float* __restrict__ Wcat,
                                             const float* __restrict__ Wexp)
{
    const int bx = blockIdx.x;
    if (bx < 16384) {
        const float* src;
        unsigned char* dst;
        int idx;
        if (bx < 8192) {            // CNN: 65536 rows x 32 k4
            idx = bx * 256 + threadIdx.x;
            int r = idx >> 5;
            int j = r >> 14, b = (r >> 9) & 31, s = r & 511;
            src = cnn + ((size_t)(b * 2048 + j * 512 + s) << 7);
            dst = g_a0 + (size_t)r * 256;
        } else {                    // 16384 rows x 32 k4 each
            int grp = (bx - 8192) >> 11;            // 0..3
            idx = ((bx - 8192) & 2047) * 256 + threadIdx.x;
            int rr = idx >> 5;
            const float* base = (grp == 0) ? gaz : (grp == 1) ? gazb : (grp == 2) ? gm : expi;
            unsigned char* pl  = (grp == 0) ? g_agf : (grp == 1) ? g_agb : (grp == 2) ? g_agm : g_aex;
            src = base + ((size_t)rr << 7);
            dst = pl + (size_t)rr * 256;
        }
        int k4 = idx & 31;
        float4 v = *reinterpret_cast<const float4*>(src + k4 * 4);
        __half2 h0 = __floats2half2_rn(v.x, v.y);
        __half2 h1 = __floats2half2_rn(v.z, v.w);
        *reinterpret_cast<uint2*>(dst + k4 * 8) =
            make_uint2(*reinterpret_cast<uint32_t*>(&h0), *reinterpret_cast<uint32_t*>(&h1));
    } else {
        // weights -> g_wh, columns reordered n' = h*4+g
        int idx = (bx - 16384) * 256 + threadIdx.x;
        int h = idx & 127;
        int k = (idx >> 7) & 511;
        int j = idx >> 16;
#pragma unroll
        for (int g = 0; g < 4; g++) {
            float v;
            if (k < 384)     v = Wcat[(size_t)k * 2048 + j * 512 + g * 128 + h];
            else if (g >= 1) v = Wexp[(size_t)(k - 384) * 1536 + j * 384 + (g - 1) * 128 + h];
            else             v = 0.f;
            int npr = h * 4 + g;
            *reinterpret_cast<__half*>(g_wh + ((size_t)(j * 512) + npr) * 1024 + k * 2) =
                __float2half_rn(v);
        }
    }
}

// ---------- Main: 3-stage pipelined fp16 HMMA GEMM + B-frag double buffer ----------
__global__ void __launch_bounds__(256, 2)
layergate_mma(const float* __restrict__ cnn,
              const float* __restrict__ expi,
              const float* __restrict__ bcat,
              const float* __restrict__ bexp,
              float* __restrict__ out)
{
    extern __shared__ __align__(1024) unsigned char smem[];
    const uint32_t sbase = smem_u32(smem);
    const int tid  = threadIdx.x;
    const int lane = tid & 31;
    const int wid  = tid >> 5;
    const int wm   = wid & 3;     // 4 warps in M (32 rows each)
    const int wn   = wid >> 2;    // 2 warps in N (64 cols each)
    const int nt   = blockIdx.x;  // 0..3   (h-block of 32)
    const int mx   = blockIdx.y;  // 0..127 (128-row tile within j)
    const int j    = blockIdx.z;  // 0..3
    const int rbase = j * 16384 + mx * 128;
    const int b    = mx >> 2;           // batch of this tile
    const int s0   = (mx & 3) * 128;    // sequence offset of row 0

    // Per-chunk A plane row-0 pointers (row stride 256B)
    const unsigned char* aplane[4];
    aplane[0] = g_a0 + (size_t)rbase * 256;
    aplane[1] = ((j & 1) ? g_agb : g_agf) + (size_t)(b * 512 + s0) * 256;
    aplane[2] = g_agm + (size_t)(b * 512 + s0) * 256;
    aplane[3] = g_aex + (size_t)(b * 512 + s0) * 256;

    float acc[2][8][4];
#pragma unroll
    for (int mf = 0; mf < 2; mf++)
#pragma unroll
        for (int nf = 0; nf < 8; nf++)
#pragma unroll
            for (int c = 0; c < 4; c++) acc[mf][nf][c] = 0.f;

    // ---- cp.async stage loader: A 16KB (1024 chunks) + B 16KB (1024 chunks)
    auto issue_stage = [&](int s) {
        const int buf = s % NSTAGE;
        const uint32_t dstStage = sbase + buf * STAGE_BYTES;
        const unsigned char* ap = aplane[s >> 1];
        const int koffB = (s & 1) * 128;          // byte offset within 256B plane row
#pragma unroll
        for (int i = 0; i < 4; i++) {
            int c = i * 256 + tid;                 // 1024 A chunks
            int r = c >> 3, ch = c & 7;
            const unsigned char* src = ap + (size_t)r * 256 + koffB + ch * 16;
            cp16(dstStage + r * 128 + ((ch ^ (r & 7)) * 16), src);
        }
#pragma unroll
        for (int i = 0; i < 4; i++) {
            int c = i * 256 + tid;                 // 1024 B chunks
            int r = c >> 3, ch = c & 7;
            const unsigned char* src =
                g_wh + ((size_t)(j * 512) + nt * 128 + r) * 1024 + s * 128 + ch * 16;
            cp16(dstStage + 16384 + r * 128 + ((ch ^ (r & 7)) * 16), src);
        }
        cp_commit();
    };

    // ldmatrix lane geometry
    const int arow = lane & 15;
    const int ac   = lane >> 4;
    const int brow = (lane & 7) | ((lane >> 4) << 3);
    const int bc   = (lane >> 3) & 1;

    auto compute_stage = [&](int s) {
        const int buf = s % NSTAGE;
        const uint32_t st = sbase + buf * STAGE_BYTES;
        const uint32_t aBase = st + (wm * 32 + arow) * 128;
        const uint32_t bBase = st + 16384 + (wn * 64 + brow) * 128;

        uint32_t B[2][8][2];
        // preload B fragments for kk = 0
        {
            const uint32_t boff = (((uint32_t)bc) ^ (uint32_t)(brow & 7)) * 16;
#pragma unroll
            for (int ng = 0; ng < 4; ng++) {
                uint32_t t[4];
                ldsm4(t, bBase + ng * 2048 + boff);
                B[0][2 * ng][0] = t[0]; B[0][2 * ng][1] = t[1];
                B[0][2 * ng + 1][0] = t[2]; B[0][2 * ng + 1][1] = t[3];
            }
        }
#pragma unroll
        for (int kk = 0; kk < 4; kk++) {
            const int cur = kk & 1, nxt = cur ^ 1;
            uint32_t A[2][4];
            const uint32_t aoff = ((kk * 2 + ac) ^ (arow & 7)) * 16;
#pragma unroll
            for (int mf = 0; mf < 2; mf++) ldsm4(A[mf], aBase + mf * 2048 + aoff);
            if (kk < 3) {   // prefetch next kk's B fragments before this kk's MMAs
                const uint32_t boff = (((kk + 1) * 2 + bc) ^ (brow & 7)) * 16;
#pragma unroll
                for (int ng = 0; ng < 4; ng++) {
                    uint32_t t[4];
                    ldsm4(t, bBase + ng * 2048 + boff);
                    B[nxt][2 * ng][0] = t[0]; B[nxt][2 * ng][1] = t[1];
                    B[nxt][2 * ng + 1][0] = t[2]; B[nxt][2 * ng + 1][1] = t[3];
                }
            }
#pragma unroll
            for (int mf = 0; mf < 2; mf++)
#pragma unroll
                for (int nf = 0; nf < 8; nf++)
                    mma_fp16(acc[mf][nf], A[mf], B[cur][nf]);
        }
    };

    issue_stage(0);
    issue_stage(1);
    for (int s = 0; s < 8; s++) {
        cp_wait1();                      // stage s landed (stage s+1 may still fly)
        __syncthreads();                 // all warps past compute(s-1); buf (s+2)%3 free
        if (s + 2 < 8) issue_stage(s + 2);
        else           cp_commit();      // empty group keeps wait arithmetic exact
        compute_stage(s);
    }

    // ---- Epilogue phase 1: dump acc to smem gate tile [128 rows][128 n'] fp32
    __syncthreads();
    float* gate = reinterpret_cast<float*>(smem);
    const int gid = lane >> 2, tig = lane & 3;
#pragma unroll
    for (int mf = 0; mf < 2; mf++)
#pragma unroll
        for (int nf = 0; nf < 8; nf++) {
            int row = wm * 32 + mf * 16 + gid;
            int col = wn * 64 + nf * 8 + tig * 2;
            *reinterpret_cast<float2*>(gate + row * 128 + col) =
                make_float2(acc[mf][nf][0], acc[mf][nf][1]);
            *reinterpret_cast<float2*>(gate + (row + 8) * 128 + col) =
                make_float2(acc[mf][nf][2], acc[mf][nf][3]);
        }
    __syncthreads();

    // ---- Epilogue phase 2: per (row, h) gather float4 {ns,g1,g2,g3}, finish, store
    const int hl = lane;
    const int hg = nt * 32 + hl;
    const float bc0 = bcat[j * 512 + hg];
    const float bc1 = bcat[j * 512 + 128 + hg];
    const float bc2 = bcat[j * 512 + 256 + hg];
    const float bc3 = bcat[j * 512 + 384 + hg];
    const float be1 = bexp[j * 384 + hg];
    const float be2 = bexp[j * 384 + 128 + hg];
    const float be3 = bexp[j * 384 + 256 + hg];
#pragma unroll
    for (int i = 0; i < 16; i++) {
        const int row = wid * 16 + i;
        const int srow = s0 + row;
        float4 gv = *reinterpret_cast<const float4*>(gate + row * 128 + hl * 4);
        float s1 = cnn[((size_t)(b * 2048 + j * 512 + srow) << 7) + hg];
        float s2 = expi[((size_t)(b * 512 + srow) << 7) + hg];
        float ns = tanhf(gv.x + bc0);
        float g1 = 1.f / (1.f + __expf(-(gv.y + bc1 + be1)));
        float g2 = 1.f / (1.f + __expf(-(gv.z + bc2 + be2)));
        float g3 = 1.f / (1.f + __expf(-(gv.w + bc3 + be3)));
        float e1 = __expf(g1), e2 = __expf(g2), e3 = __expf(g3);
        float inv = 1.f / (e1 + e2 + e3);
        out[((size_t)(rbase + row) << 7) + hg] = (e1 * ns + e2 * s1 + e3 * s2) * inv;
    }
}

extern "C" void kernel_launch(void* const* d_in, const int* in_sizes, int n_in,
                              void* d_out, int out_size)
{
    const float* cnn  = (const float*)d_in[0];
    const float* gaz  = (const float*)d_in[1];
    const float* gazb = (const float*)d_in[2];
    const float* gm   = (const float*)d_in[3];
    const float* expi = (const float*)d_in[4];
    const float* Wcat = (const float*)d_in[5];
    const float* bcat = (const float*)d_in[6];
    const float* Wexp = (const float*)d_in[7];
    const float* bexp = (const float*)d_in[8];
    float* out = (float*)d_out;

    wprep<<<17408, 256>>>(cnn, gaz, gazb, gm, expi, Wcat, Wexp);

    cudaFuncSetAttribute(layergate_mma,
                         cudaFuncAttributeMaxDynamicSharedMemorySize, SMEM_TOTAL);
    layergate_mma<<<dim3(4, 128, 4), 256, SMEM_TOTAL>>>(cnn, expi, bcat, bexp, out);
}